// round 1
// baseline (speedup 1.0000x reference)
#include <cuda_runtime.h>
#include <math.h>
#include <stdint.h>

#define NN 100000
#define NE 1600000
#define NF 256
#define NH 128
#define NC 41

#define SCAN_TILE 1024
#define NSB ((NN + SCAN_TILE - 1) / SCAN_TILE)

// ---------------- device scratch (static; no allocations allowed) ----------
__device__ float g_deg[NN];
__device__ float g_dinv[NN];
__device__ int   g_cnt[NN];
__device__ int   g_rowptr[NN + 1];
__device__ int   g_cursor[NN];
__device__ int   g_bsum[NSB];
__device__ int   g_boff[NSB];
__device__ int   g_csrc[NE];
__device__ float g_cw[NE];
__device__ float g_hs[NN * NH];   // dinv * (x @ W1)
__device__ float g_hr[NN * NH];   // relu(layer1 out)
__device__ float g_gs[NN * NC];   // dinv * (hr @ W2)

// ---------------- degree / histogram ---------------------------------------
__global__ void k_init() {
    int i = blockIdx.x * blockDim.x + threadIdx.x;
    if (i < NN) { g_deg[i] = 1.0f; g_cnt[i] = 0; }   // self-loop weight 1
}

__global__ void k_hist(const int* __restrict__ ei, const float* __restrict__ ew) {
    int e = blockIdx.x * blockDim.x + threadIdx.x;
    if (e < NE) {
        int dst = ei[NE + e];
        atomicAdd(&g_deg[dst], ew[e]);
        atomicAdd(&g_cnt[dst], 1);
    }
}

__global__ void k_dinv() {
    int i = blockIdx.x * blockDim.x + threadIdx.x;
    if (i < NN) {
        float d = g_deg[i];
        g_dinv[i] = (d > 0.0f) ? rsqrtf(d) : 0.0f;
    }
}

// ---------------- 3-pass exclusive scan of g_cnt -> g_rowptr ---------------
__global__ void k_scan1() {
    __shared__ int sh[256];
    int b = blockIdx.x, t = threadIdx.x;
    int base = b * SCAN_TILE + t * 4;
    int s = 0;
#pragma unroll
    for (int j = 0; j < 4; j++) {
        int idx = base + j;
        if (idx < NN) s += g_cnt[idx];
    }
    sh[t] = s; __syncthreads();
    for (int off = 128; off > 0; off >>= 1) {
        if (t < off) sh[t] += sh[t + off];
        __syncthreads();
    }
    if (t == 0) g_bsum[b] = sh[0];
}

__global__ void k_scan2() {
    __shared__ int sh[NSB];
    int t = threadIdx.x;
    if (t < NSB) sh[t] = g_bsum[t];
    __syncthreads();
    if (t == 0) {
        int run = 0;
        for (int b = 0; b < NSB; b++) { int v = sh[b]; sh[b] = run; run += v; }
    }
    __syncthreads();
    if (t < NSB) g_boff[t] = sh[t];
}

__global__ void k_scan3() {
    __shared__ int sh[256];
    int b = blockIdx.x, t = threadIdx.x;
    int base = b * SCAN_TILE + t * 4;
    int v[4]; int s = 0;
#pragma unroll
    for (int j = 0; j < 4; j++) {
        int idx = base + j;
        v[j] = (idx < NN) ? g_cnt[idx] : 0;
        s += v[j];
    }
    sh[t] = s; __syncthreads();
    // inclusive Hillis-Steele scan over 256 thread sums
    for (int off = 1; off < 256; off <<= 1) {
        int add = (t >= off) ? sh[t - off] : 0;
        __syncthreads();
        sh[t] += add;
        __syncthreads();
    }
    int excl = ((t > 0) ? sh[t - 1] : 0) + g_boff[b];
#pragma unroll
    for (int j = 0; j < 4; j++) {
        int idx = base + j;
        if (idx < NN) { g_rowptr[idx] = excl; g_cursor[idx] = excl; }
        excl += v[j];
    }
    if (b == 0 && t == 0) g_rowptr[NN] = NE;
}

__global__ void k_csr(const int* __restrict__ ei, const float* __restrict__ ew) {
    int e = blockIdx.x * blockDim.x + threadIdx.x;
    if (e < NE) {
        int src = ei[e];
        int dst = ei[NE + e];
        int pos = atomicAdd(&g_cursor[dst], 1);
        g_csrc[pos] = src;
        g_cw[pos]   = ew[e];
    }
}

// ---------------- tiled fp32 GEMM, epilogue: C = dinv[m] * (A@B) -----------
// WHICH==0: A = x (ext),  C = g_hs   (K=NF, NOUT=NH)
// WHICH==1: A = g_hr,     C = g_gs   (K=NH, NOUT=NC, BN padded)
template<int BM, int BN, int BK, int TM, int TN, int K, int NOUT, int WHICH>
__global__ void k_gemm(const float* __restrict__ Aext, const float* __restrict__ B) {
    const int NT = (BM / TM) * (BN / TN);
    __shared__ float As[BK][BM + 1];
    __shared__ float Bs[BK][BN];
    const float* A = (WHICH == 0) ? Aext : g_hr;
    float*       C = (WHICH == 0) ? g_hs : g_gs;

    int tid  = threadIdx.x;
    int row0 = blockIdx.x * BM;
    int trow = tid / (BN / TN);
    int tcol = tid % (BN / TN);

    float acc[TM][TN];
#pragma unroll
    for (int i = 0; i < TM; i++)
#pragma unroll
        for (int j = 0; j < TN; j++) acc[i][j] = 0.0f;

    for (int kt = 0; kt < K; kt += BK) {
#pragma unroll
        for (int i = tid; i < BM * BK; i += NT) {
            int m = i / BK, k = i % BK;
            int gm = row0 + m;
            As[k][m] = (gm < NN) ? A[gm * K + kt + k] : 0.0f;
        }
#pragma unroll
        for (int i = tid; i < BK * BN; i += NT) {
            int k = i / BN, n = i % BN;
            Bs[k][n] = (n < NOUT) ? B[(kt + k) * NOUT + n] : 0.0f;
        }
        __syncthreads();
#pragma unroll
        for (int kk = 0; kk < BK; kk++) {
            float ra[TM], rb[TN];
#pragma unroll
            for (int i = 0; i < TM; i++) ra[i] = As[kk][trow * TM + i];
#pragma unroll
            for (int j = 0; j < TN; j++) rb[j] = Bs[kk][tcol * TN + j];
#pragma unroll
            for (int i = 0; i < TM; i++)
#pragma unroll
                for (int j = 0; j < TN; j++) acc[i][j] += ra[i] * rb[j];
        }
        __syncthreads();
    }

#pragma unroll
    for (int i = 0; i < TM; i++) {
        int gm = row0 + trow * TM + i;
        if (gm < NN) {
            float dv = g_dinv[gm];
#pragma unroll
            for (int j = 0; j < TN; j++) {
                int n = tcol * TN + j;
                if (n < NOUT) C[gm * NOUT + n] = dv * acc[i][j];
            }
        }
    }
}

// ---------------- pull aggregation layer 1 (warp per node, 128 feats) ------
__global__ void k_pull1(const float* __restrict__ b1) {
    int gw   = (blockIdx.x * blockDim.x + threadIdx.x) >> 5;
    int lane = threadIdx.x & 31;
    if (gw >= NN) return;

    int rs = g_rowptr[gw], re = g_rowptr[gw + 1];
    float4 acc = make_float4(0.f, 0.f, 0.f, 0.f);

    for (int base = rs; base < re; base += 32) {
        int cnt = re - base; if (cnt > 32) cnt = 32;
        int s = 0; float wv = 0.0f;
        if (lane < cnt) { s = g_csrc[base + lane]; wv = g_cw[base + lane]; }
        for (int j = 0; j < cnt; j++) {
            int   sj = __shfl_sync(0xffffffffu, s,  j);
            float wj = __shfl_sync(0xffffffffu, wv, j);
            float4 v = *reinterpret_cast<const float4*>(&g_hs[sj * NH + lane * 4]);
            acc.x += wj * v.x; acc.y += wj * v.y;
            acc.z += wj * v.z; acc.w += wj * v.w;
        }
    }

    float  dv   = g_dinv[gw];
    float4 self = *reinterpret_cast<const float4*>(&g_hs[gw * NH + lane * 4]);
    float4 bb   = *reinterpret_cast<const float4*>(&b1[lane * 4]);
    float4 r;
    r.x = fmaxf(dv * (acc.x + self.x) + bb.x, 0.0f);
    r.y = fmaxf(dv * (acc.y + self.y) + bb.y, 0.0f);
    r.z = fmaxf(dv * (acc.z + self.z) + bb.z, 0.0f);
    r.w = fmaxf(dv * (acc.w + self.w) + bb.w, 0.0f);
    *reinterpret_cast<float4*>(&g_hr[gw * NH + lane * 4]) = r;
}

// ---------------- pull layer 2 + bias + log_softmax (warp per node) --------
__global__ void k_pull2(const float* __restrict__ b2, float* __restrict__ out) {
    int gw   = (blockIdx.x * blockDim.x + threadIdx.x) >> 5;
    int lane = threadIdx.x & 31;
    if (gw >= NN) return;

    int rs = g_rowptr[gw], re = g_rowptr[gw + 1];
    float a0 = 0.0f, a1 = 0.0f;

    for (int base = rs; base < re; base += 32) {
        int cnt = re - base; if (cnt > 32) cnt = 32;
        int s = 0; float wv = 0.0f;
        if (lane < cnt) { s = g_csrc[base + lane]; wv = g_cw[base + lane]; }
        for (int j = 0; j < cnt; j++) {
            int   sj = __shfl_sync(0xffffffffu, s,  j);
            float wj = __shfl_sync(0xffffffffu, wv, j);
            const float* row = g_gs + sj * NC;
            a0 += wj * row[lane];
            if (lane < NC - 32) a1 += wj * row[32 + lane];
        }
    }

    float dv = g_dinv[gw];
    const float* grow = g_gs + gw * NC;
    float v0 = dv * (a0 + grow[lane]) + b2[lane];
    float v1 = (lane < NC - 32) ? (dv * (a1 + grow[32 + lane]) + b2[32 + lane])
                                : -1e30f;

    float m = fmaxf(v0, v1);
#pragma unroll
    for (int off = 16; off > 0; off >>= 1)
        m = fmaxf(m, __shfl_xor_sync(0xffffffffu, m, off));

    float s = expf(v0 - m) + ((lane < NC - 32) ? expf(v1 - m) : 0.0f);
#pragma unroll
    for (int off = 16; off > 0; off >>= 1)
        s += __shfl_xor_sync(0xffffffffu, s, off);

    float lse = logf(s);
    out[gw * NC + lane] = v0 - m - lse;
    if (lane < NC - 32) out[gw * NC + 32 + lane] = v1 - m - lse;
}

// ---------------- launch ---------------------------------------------------
extern "C" void kernel_launch(void* const* d_in, const int* in_sizes, int n_in,
                              void* d_out, int out_size) {
    const float* x  = (const float*)d_in[0];
    const int*   ei = (const int*)  d_in[1];
    const float* ew = (const float*)d_in[2];
    const float* W1 = (const float*)d_in[3];
    const float* b1 = (const float*)d_in[4];
    const float* W2 = (const float*)d_in[5];
    const float* b2 = (const float*)d_in[6];
    float* out = (float*)d_out;

    k_init<<<(NN + 255) / 256, 256>>>();
    k_hist<<<(NE + 255) / 256, 256>>>(ei, ew);
    k_dinv<<<(NN + 255) / 256, 256>>>();
    k_scan1<<<NSB, 256>>>();
    k_scan2<<<1, 128>>>();
    k_scan3<<<NSB, 256>>>();
    k_csr<<<(NE + 255) / 256, 256>>>(ei, ew);

    // layer 1: hs = dinv * (x @ W1)
    k_gemm<64, 128, 16, 8, 4, NF, NH, 0><<<(NN + 63) / 64, 256>>>(x, W1);
    k_pull1<<<(NN * 32 + 255) / 256, 256>>>(b1);

    // layer 2: gs = dinv * (hr @ W2)
    k_gemm<128, 64, 16, 8, 4, NH, NC, 1><<<(NN + 127) / 128, 256>>>(nullptr, W2);
    k_pull2<<<(NN * 32 + 255) / 256, 256>>>(b2, out);
}

// round 3
// speedup vs baseline: 1.3508x; 1.3508x over previous
#include <cuda_runtime.h>
#include <math.h>
#include <stdint.h>

#define NN 100000
#define NE 1600000
#define NF 256
#define NH 128
#define NC 41

#define SCAN_TILE 1024
#define NSB ((NN + SCAN_TILE - 1) / SCAN_TILE)

// ---------------- device scratch (static; no allocations allowed) ----------
__device__ float g_deg[NN];
__device__ float g_dinv[NN];
__device__ int   g_cnt[NN];
__device__ int   g_rowptr[NN + 1];
__device__ int   g_cursor[NN];
__device__ int   g_bsum[NSB];
__device__ int   g_boff[NSB];
__device__ int   g_csrc[NE];
__device__ float g_cw[NE];
__device__ float g_hs[NN * NH];   // dinv * (x @ W1)
__device__ float g_hr[NN * NH];   // relu(layer1 out)
__device__ float g_gs[NN * NC];   // dinv * (hr @ W2)

// ---------------- packed f32x2 helpers --------------------------------------
__device__ __forceinline__ unsigned long long pk2(float lo, float hi) {
    unsigned long long r;
    asm("mov.b64 %0, {%1, %2};" : "=l"(r) : "f"(lo), "f"(hi));
    return r;
}
__device__ __forceinline__ void upk2(unsigned long long v, float& lo, float& hi) {
    asm("mov.b64 {%0, %1}, %2;" : "=f"(lo), "=f"(hi) : "l"(v));
}
__device__ __forceinline__ void ffma2(unsigned long long& d,
                                      unsigned long long a,
                                      unsigned long long b) {
    asm("fma.rn.f32x2 %0, %1, %2, %0;" : "+l"(d) : "l"(a), "l"(b));
}

// ---------------- degree / histogram ---------------------------------------
__global__ void k_init() {
    int i = blockIdx.x * blockDim.x + threadIdx.x;
    if (i < NN) { g_deg[i] = 1.0f; g_cnt[i] = 0; }   // self-loop weight 1
}

__global__ void k_hist(const int* __restrict__ ei, const float* __restrict__ ew) {
    int e = blockIdx.x * blockDim.x + threadIdx.x;
    if (e < NE) {
        int dst = ei[NE + e];
        atomicAdd(&g_deg[dst], ew[e]);
        atomicAdd(&g_cnt[dst], 1);
    }
}

__global__ void k_dinv() {
    int i = blockIdx.x * blockDim.x + threadIdx.x;
    if (i < NN) {
        float d = g_deg[i];
        g_dinv[i] = (d > 0.0f) ? rsqrtf(d) : 0.0f;
    }
}

// ---------------- 3-pass exclusive scan of g_cnt -> g_rowptr ---------------
__global__ void k_scan1() {
    __shared__ int sh[256];
    int b = blockIdx.x, t = threadIdx.x;
    int base = b * SCAN_TILE + t * 4;
    int s = 0;
#pragma unroll
    for (int j = 0; j < 4; j++) {
        int idx = base + j;
        if (idx < NN) s += g_cnt[idx];
    }
    sh[t] = s; __syncthreads();
    for (int off = 128; off > 0; off >>= 1) {
        if (t < off) sh[t] += sh[t + off];
        __syncthreads();
    }
    if (t == 0) g_bsum[b] = sh[0];
}

__global__ void k_scan2() {
    __shared__ int sh[NSB];
    int t = threadIdx.x;
    if (t < NSB) sh[t] = g_bsum[t];
    __syncthreads();
    if (t == 0) {
        int run = 0;
        for (int b = 0; b < NSB; b++) { int v = sh[b]; sh[b] = run; run += v; }
    }
    __syncthreads();
    if (t < NSB) g_boff[t] = sh[t];
}

__global__ void k_scan3() {
    __shared__ int sh[256];
    int b = blockIdx.x, t = threadIdx.x;
    int base = b * SCAN_TILE + t * 4;
    int v[4]; int s = 0;
#pragma unroll
    for (int j = 0; j < 4; j++) {
        int idx = base + j;
        v[j] = (idx < NN) ? g_cnt[idx] : 0;
        s += v[j];
    }
    sh[t] = s; __syncthreads();
    for (int off = 1; off < 256; off <<= 1) {
        int add = (t >= off) ? sh[t - off] : 0;
        __syncthreads();
        sh[t] += add;
        __syncthreads();
    }
    int excl = ((t > 0) ? sh[t - 1] : 0) + g_boff[b];
#pragma unroll
    for (int j = 0; j < 4; j++) {
        int idx = base + j;
        if (idx < NN) { g_rowptr[idx] = excl; g_cursor[idx] = excl; }
        excl += v[j];
    }
    if (b == 0 && t == 0) g_rowptr[NN] = NE;
}

__global__ void k_csr(const int* __restrict__ ei, const float* __restrict__ ew) {
    int e = blockIdx.x * blockDim.x + threadIdx.x;
    if (e < NE) {
        int src = ei[e];
        int dst = ei[NE + e];
        int pos = atomicAdd(&g_cursor[dst], 1);
        g_csrc[pos] = src;
        g_cw[pos]   = ew[e];
    }
}

// ---------------- packed-f32x2 tiled GEMM: C = dinv[m] * (A@B) -------------
// Accumulators packed along M (pairs of adjacent rows).
// WHICH==0: A = x (ext),  C = g_hs   (K=NF, NOUT=NH)
// WHICH==1: A = g_hr,     C = g_gs   (K=NH, NOUT=NC<=BN)
template<int BM, int BN, int BK, int TM, int TN, int K, int NOUT, int WHICH>
__global__ void k_gemm_p(const float* __restrict__ Aext, const float* __restrict__ B) {
    const int NT = (BM / TM) * (BN / TN);
    // +2 float pad: keeps rows 8B-aligned for float2 reads AND makes the
    // transposed write pattern bank-conflict-free ((2k+m) % 32 distinct).
    __shared__ float As[BK][BM + 2];
    __shared__ float Bs[BK][BN];
    const float* A = (WHICH == 0) ? Aext : g_hr;
    float*       C = (WHICH == 0) ? g_hs : g_gs;

    int tid  = threadIdx.x;
    int row0 = blockIdx.x * BM;
    int trow = tid / (BN / TN);
    int tcol = tid % (BN / TN);

    unsigned long long acc[TM / 2][TN];
#pragma unroll
    for (int i = 0; i < TM / 2; i++)
#pragma unroll
        for (int j = 0; j < TN; j++) acc[i][j] = 0ull;

    for (int kt = 0; kt < K; kt += BK) {
#pragma unroll 4
        for (int i = tid; i < BM * BK; i += NT) {
            int m = i / BK, k = i % BK;
            int gm = row0 + m;
            As[k][m] = (gm < NN) ? A[gm * K + kt + k] : 0.0f;
        }
#pragma unroll 4
        for (int i = tid; i < BK * BN; i += NT) {
            int k = i / BN, n = i % BN;
            Bs[k][n] = (n < NOUT) ? B[(kt + k) * NOUT + n] : 0.0f;
        }
        __syncthreads();
#pragma unroll
        for (int kk = 0; kk < BK; kk++) {
            // A: TM/2 packed pairs, 8B-aligned broadcast loads
            unsigned long long ra[TM / 2];
            const float2* ap = reinterpret_cast<const float2*>(&As[kk][trow * TM]);
#pragma unroll
            for (int i = 0; i < TM / 2; i++) {
                float2 v = ap[i];
                ra[i] = pk2(v.x, v.y);
            }
            // B: one float4 load, broadcast-packed
            float4 bv = *reinterpret_cast<const float4*>(&Bs[kk][tcol * TN]);
            unsigned long long rb[TN];
            rb[0] = pk2(bv.x, bv.x);
            rb[1] = pk2(bv.y, bv.y);
            rb[2] = pk2(bv.z, bv.z);
            rb[3] = pk2(bv.w, bv.w);
#pragma unroll
            for (int i = 0; i < TM / 2; i++)
#pragma unroll
                for (int j = 0; j < TN; j++)
                    ffma2(acc[i][j], ra[i], rb[j]);
        }
        __syncthreads();
    }

    // epilogue: scale by dinv, write both packed rows
#pragma unroll
    for (int i = 0; i < TM / 2; i++) {
        int m0 = row0 + trow * TM + 2 * i;
        int m1 = m0 + 1;
        float r0[TN], r1[TN];
#pragma unroll
        for (int j = 0; j < TN; j++) upk2(acc[i][j], r0[j], r1[j]);
        if (m0 < NN) {
            float dv = g_dinv[m0];
            if (NOUT == BN && TN == 4) {
                float4 o = make_float4(dv * r0[0], dv * r0[1], dv * r0[2], dv * r0[3]);
                *reinterpret_cast<float4*>(&C[m0 * NOUT + tcol * TN]) = o;
            } else {
#pragma unroll
                for (int j = 0; j < TN; j++) {
                    int n = tcol * TN + j;
                    if (n < NOUT) C[m0 * NOUT + n] = dv * r0[j];
                }
            }
        }
        if (m1 < NN) {
            float dv = g_dinv[m1];
            if (NOUT == BN && TN == 4) {
                float4 o = make_float4(dv * r1[0], dv * r1[1], dv * r1[2], dv * r1[3]);
                *reinterpret_cast<float4*>(&C[m1 * NOUT + tcol * TN]) = o;
            } else {
#pragma unroll
                for (int j = 0; j < TN; j++) {
                    int n = tcol * TN + j;
                    if (n < NOUT) C[m1 * NOUT + n] = dv * r1[j];
                }
            }
        }
    }
}

// ---------------- pull aggregation layer 1 (warp per node, 128 feats) ------
__global__ void k_pull1(const float* __restrict__ b1) {
    int gw   = (blockIdx.x * blockDim.x + threadIdx.x) >> 5;
    int lane = threadIdx.x & 31;
    if (gw >= NN) return;

    int rs = g_rowptr[gw], re = g_rowptr[gw + 1];
    float4 acc = make_float4(0.f, 0.f, 0.f, 0.f);

    for (int base = rs; base < re; base += 32) {
        int cnt = re - base; if (cnt > 32) cnt = 32;
        int s = 0; float wv = 0.0f;
        if (lane < cnt) { s = g_csrc[base + lane]; wv = g_cw[base + lane]; }
        for (int j = 0; j < cnt; j++) {
            int   sj = __shfl_sync(0xffffffffu, s,  j);
            float wj = __shfl_sync(0xffffffffu, wv, j);
            float4 v = *reinterpret_cast<const float4*>(&g_hs[sj * NH + lane * 4]);
            acc.x += wj * v.x; acc.y += wj * v.y;
            acc.z += wj * v.z; acc.w += wj * v.w;
        }
    }

    float  dv   = g_dinv[gw];
    float4 self = *reinterpret_cast<const float4*>(&g_hs[gw * NH + lane * 4]);
    float4 bb   = *reinterpret_cast<const float4*>(&b1[lane * 4]);
    float4 r;
    r.x = fmaxf(dv * (acc.x + self.x) + bb.x, 0.0f);
    r.y = fmaxf(dv * (acc.y + self.y) + bb.y, 0.0f);
    r.z = fmaxf(dv * (acc.z + self.z) + bb.z, 0.0f);
    r.w = fmaxf(dv * (acc.w + self.w) + bb.w, 0.0f);
    *reinterpret_cast<float4*>(&g_hr[gw * NH + lane * 4]) = r;
}

// ---------------- pull layer 2 + bias + log_softmax (warp per node) --------
__global__ void k_pull2(const float* __restrict__ b2, float* __restrict__ out) {
    int gw   = (blockIdx.x * blockDim.x + threadIdx.x) >> 5;
    int lane = threadIdx.x & 31;
    if (gw >= NN) return;

    int rs = g_rowptr[gw], re = g_rowptr[gw + 1];
    float a0 = 0.0f, a1 = 0.0f;

    for (int base = rs; base < re; base += 32) {
        int cnt = re - base; if (cnt > 32) cnt = 32;
        int s = 0; float wv = 0.0f;
        if (lane < cnt) { s = g_csrc[base + lane]; wv = g_cw[base + lane]; }
        for (int j = 0; j < cnt; j++) {
            int   sj = __shfl_sync(0xffffffffu, s,  j);
            float wj = __shfl_sync(0xffffffffu, wv, j);
            const float* row = g_gs + sj * NC;
            a0 += wj * row[lane];
            if (lane < NC - 32) a1 += wj * row[32 + lane];
        }
    }

    float dv = g_dinv[gw];
    const float* grow = g_gs + gw * NC;
    float v0 = dv * (a0 + grow[lane]) + b2[lane];
    float v1 = (lane < NC - 32) ? (dv * (a1 + grow[32 + lane]) + b2[32 + lane])
                                : -1e30f;

    float m = fmaxf(v0, v1);
#pragma unroll
    for (int off = 16; off > 0; off >>= 1)
        m = fmaxf(m, __shfl_xor_sync(0xffffffffu, m, off));

    float s = expf(v0 - m) + ((lane < NC - 32) ? expf(v1 - m) : 0.0f);
#pragma unroll
    for (int off = 16; off > 0; off >>= 1)
        s += __shfl_xor_sync(0xffffffffu, s, off);

    float lse = logf(s);
    out[gw * NC + lane] = v0 - m - lse;
    if (lane < NC - 32) out[gw * NC + 32 + lane] = v1 - m - lse;
}

// ---------------- launch ---------------------------------------------------
extern "C" void kernel_launch(void* const* d_in, const int* in_sizes, int n_in,
                              void* d_out, int out_size) {
    const float* x  = (const float*)d_in[0];
    const int*   ei = (const int*)  d_in[1];
    const float* ew = (const float*)d_in[2];
    const float* W1 = (const float*)d_in[3];
    const float* b1 = (const float*)d_in[4];
    const float* W2 = (const float*)d_in[5];
    const float* b2 = (const float*)d_in[6];
    float* out = (float*)d_out;

    k_init<<<(NN + 255) / 256, 256>>>();
    k_hist<<<(NE + 255) / 256, 256>>>(ei, ew);
    k_dinv<<<(NN + 255) / 256, 256>>>();
    k_scan1<<<NSB, 256>>>();
    k_scan2<<<1, 128>>>();
    k_scan3<<<NSB, 256>>>();
    k_csr<<<(NE + 255) / 256, 256>>>(ei, ew);

    // layer 1: hs = dinv * (x @ W1)  — f32x2 packed, 256 threads
    k_gemm_p<128, 128, 16, 16, 4, NF, NH, 0><<<(NN + 127) / 128, 256>>>(x, W1);
    k_pull1<<<(NN * 32 + 255) / 256, 256>>>(b1);

    // layer 2: gs = dinv * (hr @ W2) — f32x2 packed, 128 threads
    k_gemm_p<128, 64, 16, 16, 4, NH, NC, 1><<<(NN + 127) / 128, 128>>>(nullptr, W2);
    k_pull2<<<(NN * 32 + 255) / 256, 256>>>(b2, out);
}